// round 13
// baseline (speedup 1.0000x reference)
#include <cuda_runtime.h>
#include <cuda_fp16.h>

#define B_ROWS   16384
#define K_FEATS  32
#define H_DIM    256
#define FULLMASK 0xFFFFFFFFu

#define TILE      16        // rows per block (1 row per warp, 16 warps)
#define NTHREADS  512
#define XS_STRIDE 516       // floats per staged row (512 + 4 pad, conflict-free)

#define TBL_BLOCKS 5120     // blocks of prep_all doing the fp16 table

// fp16 copy of ft_w: 40960 x 256 halves = 20MB (128 half2 per row)
__device__ __half2 g_ftw_h[40960 * 128];
// fc1_w transposed: [iq][j] float4 (iq over 512/4 inputs, j = 0..31 outputs)
__device__ float4 g_fc1T[128 * 32];

// ---- merged prep: fp16 table (blocks < TBL_BLOCKS) + fc1 transpose (rest) ----
// __ldg: ft_w stays L2-resident across graph replays (40+20 MB << 126 MB L2).
__global__ __launch_bounds__(256) void prep_all(const float* __restrict__ ft_w,
                                                const float* __restrict__ fc1_w) {
    const int b = blockIdx.x;
    if (b < TBL_BLOCKS) {
        int i = b * blockDim.x + threadIdx.x;   // over 1,310,720 8-float chunks
        const float4 v0 = __ldg((const float4*)ft_w + i * 2);
        const float4 v1 = __ldg((const float4*)ft_w + i * 2 + 1);
        uint4 r;
        __half2 h0 = __floats2half2_rn(v0.x, v0.y);
        __half2 h1 = __floats2half2_rn(v0.z, v0.w);
        __half2 h2 = __floats2half2_rn(v1.x, v1.y);
        __half2 h3 = __floats2half2_rn(v1.z, v1.w);
        r.x = *(unsigned*)&h0; r.y = *(unsigned*)&h1;
        r.z = *(unsigned*)&h2; r.w = *(unsigned*)&h3;
        ((uint4*)g_ftw_h)[i] = r;
    } else {
        int t = (b - TBL_BLOCKS) * blockDim.x + threadIdx.x;
        if (t < 128 * 32) {
            int iq = t >> 5;
            int j  = t & 31;
            const float* p = fc1_w + j * 512 + iq * 4;
            g_fc1T[t] = make_float4(p[0], p[1], p[2], p[3]);
        }
    }
    cudaTriggerProgrammaticLaunchCompletion();
}

__device__ __forceinline__ float4 clip01(float4 v) {
    v.x = fminf(fmaxf(v.x, 0.0f), 1.0f);
    v.y = fminf(fmaxf(v.y, 0.0f), 1.0f);
    v.z = fminf(fmaxf(v.z, 0.0f), 1.0f);
    v.w = fminf(fmaxf(v.w, 0.0f), 1.0f);
    return v;
}

// accumulate 8 fp16 values (one uint4) scaled by m into two float4 accumulators
__device__ __forceinline__ void acc8(float4& a0, float4& a1, float m, uint4 r) {
    const __half2* h = (const __half2*)&r;
    float2 f0 = __half22float2(h[0]);
    float2 f1 = __half22float2(h[1]);
    float2 f2 = __half22float2(h[2]);
    float2 f3 = __half22float2(h[3]);
    a0.x = fmaf(m, f0.x, a0.x);  a0.y = fmaf(m, f0.y, a0.y);
    a0.z = fmaf(m, f1.x, a0.z);  a0.w = fmaf(m, f1.y, a0.w);
    a1.x = fmaf(m, f2.x, a1.x);  a1.y = fmaf(m, f2.y, a1.y);
    a1.z = fmaf(m, f3.x, a1.z);  a1.w = fmaf(m, f3.y, a1.w);
}

__global__ __launch_bounds__(NTHREADS, 2)
void nnue_kernel(const int*   __restrict__ wft_ics,
                 const float* __restrict__ wft_vals,
                 const int*   __restrict__ bft_ics,
                 const float* __restrict__ bft_vals,
                 const int*   __restrict__ stm,
                 const float* __restrict__ ft_b,
                 const float* __restrict__ fc1_b,
                 const float* __restrict__ fc2_w,
                 const float* __restrict__ fc2_b,
                 const float* __restrict__ fco_w,
                 const float* __restrict__ fco_b,
                 float*       __restrict__ out)
{
    // s_feat[r][k] = (w_off_half2, w_val_bits, b_off_half2, b_val_bits); padded -> val_bits=0
    __shared__ int4  s_feat[TILE][K_FEATS];     // 8 KB
    __shared__ float xs[TILE * XS_STRIDE];      // staged x[512]/row fp32, padded  33 KB
    __shared__ float fc2T[32 * 33];             // fc2T[i*33+j] = fc2_w[j][i]; pad: W+R conflict-free
    __shared__ float h1s[TILE * 33];            // clipped FC1 activations
    __shared__ int   s_stm[TILE];

    const int tid  = threadIdx.x;
    const int lane = tid & 31;
    const int warp = tid >> 5;               // 0..15
    const int row0 = blockIdx.x * TILE;

    // ---- staging (reads only harness inputs; independent of prep_all's outputs) ----
    for (int idx = tid; idx < 1024; idx += NTHREADS) {
        // idx = j*32 + i  ->  fc2T[i*33 + j]; stride-33 store: distinct banks per thread
        fc2T[(idx & 31) * 33 + (idx >> 5)] = fc2_w[idx];
    }
    if (tid < TILE)
        s_stm[tid] = stm[row0 + tid];

    // one (r,k) entry per thread: 16*32 = 512
    {
        const int r  = tid >> 5;
        const int k  = tid & 31;
        const int gi = (row0 + r) * K_FEATS + k;
        const int   wi = __ldg(wft_ics + gi);
        const float wv = __ldg(wft_vals + gi);
        const int   bi = __ldg(bft_ics + gi);
        const float bv = __ldg(bft_vals + gi);
        s_feat[r][k] = make_int4(wi >= 0 ? wi * 128 : 0,
                                 __float_as_int(wi >= 0 ? wv : 0.0f),
                                 bi >= 0 ? bi * 128 : 0,
                                 __float_as_int(bi >= 0 ? bv : 0.0f));
    }

    // per-lane ft bias (cols lane*8 .. lane*8+7)
    const float4 bias0 = *(const float4*)(ft_b + lane * 8);
    const float4 bias1 = *(const float4*)(ft_b + lane * 8 + 4);

    __syncthreads();

    // PDL: wait for prep_all's g_ftw_h / g_fc1T writes before reading them
    cudaGridDependencySynchronize();

    // ---------------- Phase 1: gather (warp r -> row r; 16 acc floats) ----------------
    {
        const int r = warp;

        float4 aw0 = bias0, aw1 = bias1;
        float4 ab0 = bias0, ab1 = bias1;

        #pragma unroll 4
        for (int k = 0; k < K_FEATS; k++) {
            const int4 f = s_feat[r][k];     // broadcast LDS.128 (warp-uniform)
            // uniform skip of padded slots (val bits == 0): no divergence
            if (f.y != 0) {
                const uint4 rw = __ldcg((const uint4*)(g_ftw_h + f.x) + lane);
                acc8(aw0, aw1, __int_as_float(f.y), rw);
            }
            if (f.w != 0) {
                const uint4 rb = __ldcg((const uint4*)(g_ftw_h + f.z) + lane);
                acc8(ab0, ab1, __int_as_float(f.w), rb);
            }
        }

        // stm-conditional swap + clip, store fp32 x
        const int s = s_stm[r];
        float4 lo0, lo1, hi0, hi1;
        if (s) { lo0 = ab0; lo1 = ab1; hi0 = aw0; hi1 = aw1; }
        else   { lo0 = aw0; lo1 = aw1; hi0 = ab0; hi1 = ab1; }

        float4* xr = (float4*)(xs + r * XS_STRIDE);
        xr[lane * 2]          = clip01(lo0);
        xr[lane * 2 + 1]      = clip01(lo1);
        xr[64 + lane * 2]     = clip01(hi0);
        xr[64 + lane * 2 + 1] = clip01(hi1);
    }

    __syncthreads();

    // ---------------- Phase 2: FC1 --------------------------------------------------
    // warp: g = warp&3 (output group of 8), q = warp>>2 (row quarter of 4)
    // lane: rg = lane>>3 (row in quarter), jo = lane&7 (output in group)
    // thread -> row q*4+rg, output j = g*8+jo
    // Weight per iq: 8 consecutive float4 = one 128B line per warp, 4-way bcast, L1-hot.
    // xs per iq: 4 distinct rows, bank offsets {0,4,8,12} (516 mod 32 = 4) -> conflict-free.
    {
        const int jo  = lane & 7;
        const int rg  = lane >> 3;
        const int g   = warp & 3;
        const int q   = warp >> 2;
        const int j   = g * 8 + jo;
        const int row = q * 4 + rg;

        float h1 = __ldg(fc1_b + j);
        const float4* xr = (const float4*)(xs + row * XS_STRIDE);

        #pragma unroll 4
        for (int iq = 0; iq < 128; iq++) {
            const float4 w  = g_fc1T[iq * 32 + j];
            const float4 xv = xr[iq];
            h1 = fmaf(w.x, xv.x, fmaf(w.y, xv.y, fmaf(w.z, xv.z, fmaf(w.w, xv.w, h1))));
        }

        h1s[row * 33 + j] = fminf(fmaxf(h1, 0.0f), 1.0f);
    }

    __syncthreads();

    // ---------------- FC2 + output head: warp r -> row r ------------------------------
    {
        const int row = warp;
        const float b2j = __ldg(fc2_b + lane);
        const float fcw = __ldg(fco_w + lane);
        const float fcb = __ldg(fco_b);

        float h2 = b2j;
        #pragma unroll
        for (int i = 0; i < 32; i++)
            h2 = fmaf(fc2T[i * 33 + lane], h1s[row * 33 + i], h2);
        h2 = fminf(fmaxf(h2, 0.0f), 1.0f);

        float o = h2 * fcw;
        #pragma unroll
        for (int off = 16; off; off >>= 1)
            o += __shfl_xor_sync(FULLMASK, o, off);

        if (lane == 0)
            out[row0 + row] = o + fcb;
    }
}

extern "C" void kernel_launch(void* const* d_in, const int* in_sizes, int n_in,
                              void* d_out, int out_size)
{
    const int*   wft_ics  = (const int*)  d_in[0];
    const float* wft_vals = (const float*)d_in[1];
    const int*   bft_ics  = (const int*)  d_in[2];
    const float* bft_vals = (const float*)d_in[3];
    const int*   stm      = (const int*)  d_in[4];
    const float* ft_w     = (const float*)d_in[5];
    const float* ft_b     = (const float*)d_in[6];
    const float* fc1_w    = (const float*)d_in[7];
    const float* fc1_b    = (const float*)d_in[8];
    const float* fc2_w    = (const float*)d_in[9];
    const float* fc2_b    = (const float*)d_in[10];
    const float* fco_w    = (const float*)d_in[11];
    const float* fco_b    = (const float*)d_in[12];
    float* out = (float*)d_out;

    // primary: table conversion + fc1 transpose
    prep_all<<<TBL_BLOCKS + 16, 256>>>(ft_w, fc1_w);

    // secondary with programmatic dependent launch: overlaps its staging with prep tail
    cudaLaunchConfig_t cfg = {};
    cfg.gridDim  = dim3(B_ROWS / TILE);
    cfg.blockDim = dim3(NTHREADS);
    cfg.dynamicSmemBytes = 0;
    cfg.stream = 0;
    cudaLaunchAttribute attrs[1];
    attrs[0].id = cudaLaunchAttributeProgrammaticStreamSerialization;
    attrs[0].val.programmaticStreamSerializationAllowed = 1;
    cfg.attrs = attrs;
    cfg.numAttrs = 1;
    cudaLaunchKernelEx(&cfg, nnue_kernel,
                       wft_ics, wft_vals, bft_ics, bft_vals, stm,
                       ft_b, fc1_b, fc2_w, fc2_b, fco_w, fco_b, out);
}

// round 14
// speedup vs baseline: 1.1630x; 1.1630x over previous
#include <cuda_runtime.h>
#include <cuda_fp16.h>

#define B_ROWS   16384
#define K_FEATS  32
#define H_DIM    256
#define FULLMASK 0xFFFFFFFFu

#define TILE      16        // rows per block
#define XS_STRIDE 516       // floats per staged row (512 + 4 pad, conflict-free)

#define TBL_BLOCKS 5120     // blocks of prep_all doing the fp16 table

// fp16 copy of ft_w: 40960 x 256 halves = 20MB (128 half2 per row)
__device__ __half2 g_ftw_h[40960 * 128];
// fc1_w transposed: [iq][j] float4 (iq over 512/4 inputs, j = 0..31 outputs)
__device__ float4 g_fc1T[128 * 32];

// ---- merged prep: fp16 table (blocks < TBL_BLOCKS) + fc1 transpose (rest) ----
// __ldg: ft_w stays L2-resident across graph replays (40+20 MB << 126 MB L2).
__global__ __launch_bounds__(256) void prep_all(const float* __restrict__ ft_w,
                                                const float* __restrict__ fc1_w) {
    const int b = blockIdx.x;
    if (b < TBL_BLOCKS) {
        int i = b * blockDim.x + threadIdx.x;   // over 1,310,720 8-float chunks
        const float4 v0 = __ldg((const float4*)ft_w + i * 2);
        const float4 v1 = __ldg((const float4*)ft_w + i * 2 + 1);
        uint4 r;
        __half2 h0 = __floats2half2_rn(v0.x, v0.y);
        __half2 h1 = __floats2half2_rn(v0.z, v0.w);
        __half2 h2 = __floats2half2_rn(v1.x, v1.y);
        __half2 h3 = __floats2half2_rn(v1.z, v1.w);
        r.x = *(unsigned*)&h0; r.y = *(unsigned*)&h1;
        r.z = *(unsigned*)&h2; r.w = *(unsigned*)&h3;
        ((uint4*)g_ftw_h)[i] = r;
    } else {
        int t = (b - TBL_BLOCKS) * blockDim.x + threadIdx.x;
        if (t < 128 * 32) {
            int iq = t >> 5;
            int j  = t & 31;
            const float* p = fc1_w + j * 512 + iq * 4;
            g_fc1T[t] = make_float4(p[0], p[1], p[2], p[3]);
        }
    }
    cudaTriggerProgrammaticLaunchCompletion();
}

__device__ __forceinline__ float4 clip01(float4 v) {
    v.x = fminf(fmaxf(v.x, 0.0f), 1.0f);
    v.y = fminf(fmaxf(v.y, 0.0f), 1.0f);
    v.z = fminf(fmaxf(v.z, 0.0f), 1.0f);
    v.w = fminf(fmaxf(v.w, 0.0f), 1.0f);
    return v;
}

// accumulate 8 fp16 values (one uint4) scaled by m into two float4 accumulators
__device__ __forceinline__ void acc8(float4& a0, float4& a1, float m, uint4 r) {
    const __half2* h = (const __half2*)&r;
    float2 f0 = __half22float2(h[0]);
    float2 f1 = __half22float2(h[1]);
    float2 f2 = __half22float2(h[2]);
    float2 f3 = __half22float2(h[3]);
    a0.x = fmaf(m, f0.x, a0.x);  a0.y = fmaf(m, f0.y, a0.y);
    a0.z = fmaf(m, f1.x, a0.z);  a0.w = fmaf(m, f1.y, a0.w);
    a1.x = fmaf(m, f2.x, a1.x);  a1.y = fmaf(m, f2.y, a1.y);
    a1.z = fmaf(m, f3.x, a1.z);  a1.w = fmaf(m, f3.y, a1.w);
}

__global__ __launch_bounds__(256, 4)
void nnue_kernel(const int*   __restrict__ wft_ics,
                 const float* __restrict__ wft_vals,
                 const int*   __restrict__ bft_ics,
                 const float* __restrict__ bft_vals,
                 const int*   __restrict__ stm,
                 const float* __restrict__ ft_b,
                 const float* __restrict__ fc1_b,
                 const float* __restrict__ fc2_w,
                 const float* __restrict__ fc2_b,
                 const float* __restrict__ fco_w,
                 const float* __restrict__ fco_b,
                 float*       __restrict__ out)
{
    // s_feat[r][k] = (w_off_half2, w_val_bits, b_off_half2, b_val_bits); padded -> val_bits=0
    __shared__ int4  s_feat[TILE][K_FEATS];     // 8 KB
    __shared__ float xs[TILE * XS_STRIDE];      // staged x[512]/row fp32, padded  33 KB
    __shared__ float fc2T[32 * 32];             // fc2T[i*32+j] = fc2_w[j][i]      4 KB
    __shared__ float h1s[TILE * 33];            // clipped FC1 activations         2.1 KB
    __shared__ int   s_stm[TILE];

    const int tid  = threadIdx.x;
    const int lane = tid & 31;
    const int warp = tid >> 5;               // 0..7
    const int row0 = blockIdx.x * TILE;

    // ---- staging (reads only harness inputs; independent of prep_all's outputs) ----
    for (int idx = tid; idx < 1024; idx += 256)
        fc2T[(idx & 31) * 32 + (idx >> 5)] = fc2_w[idx];
    if (tid < TILE)
        s_stm[tid] = stm[row0 + tid];

    #pragma unroll
    for (int e = tid; e < TILE * K_FEATS; e += 256) {
        const int r  = e >> 5;
        const int k  = e & 31;
        const int gi = (row0 + r) * K_FEATS + k;
        const int   wi = __ldg(wft_ics + gi);
        const float wv = __ldg(wft_vals + gi);
        const int   bi = __ldg(bft_ics + gi);
        const float bv = __ldg(bft_vals + gi);
        s_feat[r][k] = make_int4(wi >= 0 ? wi * 128 : 0,
                                 __float_as_int(wi >= 0 ? wv : 0.0f),
                                 bi >= 0 ? bi * 128 : 0,
                                 __float_as_int(bi >= 0 ? bv : 0.0f));
    }

    // per-lane ft bias (cols lane*8 .. lane*8+7)
    const float4 bias0 = *(const float4*)(ft_b + lane * 8);
    const float4 bias1 = *(const float4*)(ft_b + lane * 8 + 4);

    __syncthreads();

    // PDL: wait for prep_all's g_ftw_h / g_fc1T writes before reading them
    cudaGridDependencySynchronize();

    // ---------------- Phase 1: gather (warp w -> rows 2w, 2w+1) ----------------
    #pragma unroll
    for (int rr = 0; rr < 2; rr++) {
        const int r = warp * 2 + rr;

        float4 aw0 = bias0, aw1 = bias1;
        float4 ab0 = bias0, ab1 = bias1;

        #pragma unroll 4
        for (int k = 0; k < K_FEATS; k++) {
            const int4 f = s_feat[r][k];     // broadcast LDS.128 (warp-uniform)
            // uniform skip of padded slots (val bits == 0): no divergence
            if (f.y != 0) {
                const uint4 rw = __ldcg((const uint4*)(g_ftw_h + f.x) + lane);
                acc8(aw0, aw1, __int_as_float(f.y), rw);
            }
            if (f.w != 0) {
                const uint4 rb = __ldcg((const uint4*)(g_ftw_h + f.z) + lane);
                acc8(ab0, ab1, __int_as_float(f.w), rb);
            }
        }

        // stm-conditional swap + clip, store fp32 x
        const int s = s_stm[r];
        float4 lo0, lo1, hi0, hi1;
        if (s) { lo0 = ab0; lo1 = ab1; hi0 = aw0; hi1 = aw1; }
        else   { lo0 = aw0; lo1 = aw1; hi0 = ab0; hi1 = ab1; }

        float4* xr = (float4*)(xs + r * XS_STRIDE);
        xr[lane * 2]          = clip01(lo0);
        xr[lane * 2 + 1]      = clip01(lo1);
        xr[64 + lane * 2]     = clip01(hi0);
        xr[64 + lane * 2 + 1] = clip01(hi1);
    }

    __syncthreads();

    // ---------------- Phase 2: FC1 (lane j = output j; warp w -> rows 2w, 2w+1) ------
    const int j = lane;
    const float b1j = __ldg(fc1_b + j);
    float h1a = b1j, h1b = b1j;

    const int r0 = warp * 2;
    const float4* x0 = (const float4*)(xs + r0 * XS_STRIDE);
    const float4* x1 = (const float4*)(xs + (r0 + 1) * XS_STRIDE);

    #pragma unroll 4
    for (int iq = 0; iq < 128; iq++) {
        const float4 w  = g_fc1T[iq * 32 + j];  // coalesced 512B, L1-hot
        const float4 xa = x0[iq];               // broadcast LDS.128
        const float4 xb = x1[iq];
        h1a = fmaf(w.x, xa.x, fmaf(w.y, xa.y, fmaf(w.z, xa.z, fmaf(w.w, xa.w, h1a))));
        h1b = fmaf(w.x, xb.x, fmaf(w.y, xb.y, fmaf(w.z, xb.z, fmaf(w.w, xb.w, h1b))));
    }

    h1s[r0 * 33 + j]       = fminf(fmaxf(h1a, 0.0f), 1.0f);
    h1s[(r0 + 1) * 33 + j] = fminf(fmaxf(h1b, 0.0f), 1.0f);

    __syncthreads();

    // ---------------- FC2 + output head: warp w -> rows 2w, 2w+1 ----------------------
    const float b2j = __ldg(fc2_b + lane);
    const float fcw = __ldg(fco_w + lane);
    const float fcb = __ldg(fco_b);

    #pragma unroll
    for (int rr = 0; rr < 2; rr++) {
        const int row = warp * 2 + rr;
        float h2 = b2j;
        #pragma unroll
        for (int i = 0; i < 32; i++)
            h2 = fmaf(fc2T[i * 32 + lane], h1s[row * 33 + i], h2);
        h2 = fminf(fmaxf(h2, 0.0f), 1.0f);

        float o = h2 * fcw;
        #pragma unroll
        for (int off = 16; off; off >>= 1)
            o += __shfl_xor_sync(FULLMASK, o, off);

        if (lane == 0)
            out[row0 + row] = o + fcb;
    }
}

extern "C" void kernel_launch(void* const* d_in, const int* in_sizes, int n_in,
                              void* d_out, int out_size)
{
    const int*   wft_ics  = (const int*)  d_in[0];
    const float* wft_vals = (const float*)d_in[1];
    const int*   bft_ics  = (const int*)  d_in[2];
    const float* bft_vals = (const float*)d_in[3];
    const int*   stm      = (const int*)  d_in[4];
    const float* ft_w     = (const float*)d_in[5];
    const float* ft_b     = (const float*)d_in[6];
    const float* fc1_w    = (const float*)d_in[7];
    const float* fc1_b    = (const float*)d_in[8];
    const float* fc2_w    = (const float*)d_in[9];
    const float* fc2_b    = (const float*)d_in[10];
    const float* fco_w    = (const float*)d_in[11];
    const float* fco_b    = (const float*)d_in[12];
    float* out = (float*)d_out;

    // primary: table conversion + fc1 transpose
    prep_all<<<TBL_BLOCKS + 16, 256>>>(ft_w, fc1_w);

    // secondary with programmatic dependent launch: overlaps its staging with prep tail
    cudaLaunchConfig_t cfg = {};
    cfg.gridDim  = dim3(B_ROWS / TILE);
    cfg.blockDim = dim3(256);
    cfg.dynamicSmemBytes = 0;
    cfg.stream = 0;
    cudaLaunchAttribute attrs[1];
    attrs[0].id = cudaLaunchAttributeProgrammaticStreamSerialization;
    attrs[0].val.programmaticStreamSerializationAllowed = 1;
    cfg.attrs = attrs;
    cfg.numAttrs = 1;
    cudaLaunchKernelEx(&cfg, nnue_kernel,
                       wft_ics, wft_vals, bft_ics, bft_vals, stm,
                       ft_b, fc1_b, fc2_w, fc2_b, fco_w, fco_b, out);
}

// round 15
// speedup vs baseline: 1.1635x; 1.0004x over previous
#include <cuda_runtime.h>
#include <cuda_fp16.h>

#define B_ROWS   16384
#define K_FEATS  32
#define H_DIM    256
#define FULLMASK 0xFFFFFFFFu

#define TILE      16        // rows per block
#define XS_STRIDE 516       // floats per staged row (512 + 4 pad, conflict-free)

#define TBL_BLOCKS 5120     // blocks of prep_all doing the fp16 table

// fp16 copy of ft_w: 40960 x 256 halves = 20MB (128 half2 per row)
__device__ __half2 g_ftw_h[40960 * 128];
// fc1_w transposed: [iq][j] float4 (iq over 512/4 inputs, j = 0..31 outputs)
__device__ float4 g_fc1T[128 * 32];

// ---- merged prep: fp16 table (blocks < TBL_BLOCKS) + fc1 transpose (rest) ----
// __ldg: ft_w stays L2-resident across graph replays (40+20 MB << 126 MB L2).
__global__ __launch_bounds__(256) void prep_all(const float* __restrict__ ft_w,
                                                const float* __restrict__ fc1_w) {
    const int b = blockIdx.x;
    if (b < TBL_BLOCKS) {
        int i = b * blockDim.x + threadIdx.x;   // over 1,310,720 8-float chunks
        const float4 v0 = __ldg((const float4*)ft_w + i * 2);
        const float4 v1 = __ldg((const float4*)ft_w + i * 2 + 1);
        uint4 r;
        __half2 h0 = __floats2half2_rn(v0.x, v0.y);
        __half2 h1 = __floats2half2_rn(v0.z, v0.w);
        __half2 h2 = __floats2half2_rn(v1.x, v1.y);
        __half2 h3 = __floats2half2_rn(v1.z, v1.w);
        r.x = *(unsigned*)&h0; r.y = *(unsigned*)&h1;
        r.z = *(unsigned*)&h2; r.w = *(unsigned*)&h3;
        ((uint4*)g_ftw_h)[i] = r;
    } else {
        int t = (b - TBL_BLOCKS) * blockDim.x + threadIdx.x;
        if (t < 128 * 32) {
            int iq = t >> 5;
            int j  = t & 31;
            const float* p = fc1_w + j * 512 + iq * 4;
            g_fc1T[t] = make_float4(p[0], p[1], p[2], p[3]);
        }
    }
    cudaTriggerProgrammaticLaunchCompletion();
}

__device__ __forceinline__ float4 clip01(float4 v) {
    v.x = fminf(fmaxf(v.x, 0.0f), 1.0f);
    v.y = fminf(fmaxf(v.y, 0.0f), 1.0f);
    v.z = fminf(fmaxf(v.z, 0.0f), 1.0f);
    v.w = fminf(fmaxf(v.w, 0.0f), 1.0f);
    return v;
}

// accumulate 8 fp16 values (one uint4) scaled by m into two float4 accumulators
__device__ __forceinline__ void acc8(float4& a0, float4& a1, float m, uint4 r) {
    const __half2* h = (const __half2*)&r;
    float2 f0 = __half22float2(h[0]);
    float2 f1 = __half22float2(h[1]);
    float2 f2 = __half22float2(h[2]);
    float2 f3 = __half22float2(h[3]);
    a0.x = fmaf(m, f0.x, a0.x);  a0.y = fmaf(m, f0.y, a0.y);
    a0.z = fmaf(m, f1.x, a0.z);  a0.w = fmaf(m, f1.y, a0.w);
    a1.x = fmaf(m, f2.x, a1.x);  a1.y = fmaf(m, f2.y, a1.y);
    a1.z = fmaf(m, f3.x, a1.z);  a1.w = fmaf(m, f3.y, a1.w);
}

__global__ __launch_bounds__(256, 4)
void nnue_kernel(const int*   __restrict__ wft_ics,
                 const float* __restrict__ wft_vals,
                 const int*   __restrict__ bft_ics,
                 const float* __restrict__ bft_vals,
                 const int*   __restrict__ stm,
                 const float* __restrict__ ft_b,
                 const float* __restrict__ fc1_b,
                 const float* __restrict__ fc2_w,
                 const float* __restrict__ fc2_b,
                 const float* __restrict__ fco_w,
                 const float* __restrict__ fco_b,
                 float*       __restrict__ out)
{
    // Compacted active-feature lists: (offset_in_half2, val_bits), per row, w and b.
    __shared__ int2  s_w[TILE][K_FEATS];        // 4 KB
    __shared__ int2  s_b[TILE][K_FEATS];        // 4 KB
    __shared__ int   s_wcnt[TILE], s_bcnt[TILE];
    __shared__ float xs[TILE * XS_STRIDE];      // staged x[512]/row fp32, padded  33 KB
    __shared__ float fc2T[32 * 32];             // fc2T[i*32+j] = fc2_w[j][i]      4 KB
    __shared__ float h1s[TILE * 33];            // clipped FC1 activations         2.1 KB
    __shared__ int   s_stm[TILE];

    const int tid  = threadIdx.x;
    const int lane = tid & 31;
    const int warp = tid >> 5;               // 0..7
    const int row0 = blockIdx.x * TILE;

    // ---- staging (reads only harness inputs; independent of prep_all's outputs) ----
    for (int idx = tid; idx < 1024; idx += 256)
        fc2T[(idx & 31) * 32 + (idx >> 5)] = fc2_w[idx];
    if (tid < TILE)
        s_stm[tid] = stm[row0 + tid];

    // Warp w compacts rows 2w, 2w+1: ballot + prefix-popc keeps original order,
    // so accumulation order over active features is identical to the guarded loop.
    #pragma unroll
    for (int rr = 0; rr < 2; rr++) {
        const int r  = warp * 2 + rr;
        const int gi = (row0 + r) * K_FEATS + lane;

        {
            const int   wi = __ldg(wft_ics + gi);
            const float wv = __ldg(wft_vals + gi);
            const bool  act = (wi >= 0);
            const unsigned m = __ballot_sync(FULLMASK, act);
            const int pos = __popc(m & ((1u << lane) - 1));
            if (act) s_w[r][pos] = make_int2(wi * 128, __float_as_int(wv));
            if (lane == 0) s_wcnt[r] = __popc(m);
        }
        {
            const int   bi = __ldg(bft_ics + gi);
            const float bv = __ldg(bft_vals + gi);
            const bool  act = (bi >= 0);
            const unsigned m = __ballot_sync(FULLMASK, act);
            const int pos = __popc(m & ((1u << lane) - 1));
            if (act) s_b[r][pos] = make_int2(bi * 128, __float_as_int(bv));
            if (lane == 0) s_bcnt[r] = __popc(m);
        }
    }

    // per-lane ft bias (cols lane*8 .. lane*8+7)
    const float4 bias0 = *(const float4*)(ft_b + lane * 8);
    const float4 bias1 = *(const float4*)(ft_b + lane * 8 + 4);

    __syncthreads();

    // PDL: wait for prep_all's g_ftw_h / g_fc1T writes before reading them
    cudaGridDependencySynchronize();

    // ---------------- Phase 1: gather (warp w -> rows 2w, 2w+1) ----------------
    // Guard-free loops over compacted lists: warp-uniform trip count, branchless
    // bodies, unroll-4 batches 4 independent LDG.128s for full MLP.
    #pragma unroll
    for (int rr = 0; rr < 2; rr++) {
        const int r = warp * 2 + rr;

        float4 aw0 = bias0, aw1 = bias1;
        {
            const int cw = s_wcnt[r];
            const int2* fw = s_w[r];
            #pragma unroll 4
            for (int k = 0; k < cw; k++) {
                const int2 f = fw[k];                                   // broadcast LDS.64
                const uint4 rw = __ldcg((const uint4*)(g_ftw_h + f.x) + lane);
                acc8(aw0, aw1, __int_as_float(f.y), rw);
            }
        }

        float4 ab0 = bias0, ab1 = bias1;
        {
            const int cb = s_bcnt[r];
            const int2* fb = s_b[r];
            #pragma unroll 4
            for (int k = 0; k < cb; k++) {
                const int2 f = fb[k];
                const uint4 rb = __ldcg((const uint4*)(g_ftw_h + f.x) + lane);
                acc8(ab0, ab1, __int_as_float(f.y), rb);
            }
        }

        // stm-conditional swap + clip, store fp32 x
        const int s = s_stm[r];
        float4 lo0, lo1, hi0, hi1;
        if (s) { lo0 = ab0; lo1 = ab1; hi0 = aw0; hi1 = aw1; }
        else   { lo0 = aw0; lo1 = aw1; hi0 = ab0; hi1 = ab1; }

        float4* xr = (float4*)(xs + r * XS_STRIDE);
        xr[lane * 2]          = clip01(lo0);
        xr[lane * 2 + 1]      = clip01(lo1);
        xr[64 + lane * 2]     = clip01(hi0);
        xr[64 + lane * 2 + 1] = clip01(hi1);
    }

    __syncthreads();

    // ---------------- Phase 2: FC1 (lane j = output j; warp w -> rows 2w, 2w+1) ------
    const int j = lane;
    const float b1j = __ldg(fc1_b + j);
    float h1a = b1j, h1b = b1j;

    const int r0 = warp * 2;
    const float4* x0 = (const float4*)(xs + r0 * XS_STRIDE);
    const float4* x1 = (const float4*)(xs + (r0 + 1) * XS_STRIDE);

    #pragma unroll 4
    for (int iq = 0; iq < 128; iq++) {
        const float4 w  = g_fc1T[iq * 32 + j];  // coalesced 512B, L1-hot
        const float4 xa = x0[iq];               // broadcast LDS.128
        const float4 xb = x1[iq];
        h1a = fmaf(w.x, xa.x, fmaf(w.y, xa.y, fmaf(w.z, xa.z, fmaf(w.w, xa.w, h1a))));
        h1b = fmaf(w.x, xb.x, fmaf(w.y, xb.y, fmaf(w.z, xb.z, fmaf(w.w, xb.w, h1b))));
    }

    h1s[r0 * 33 + j]       = fminf(fmaxf(h1a, 0.0f), 1.0f);
    h1s[(r0 + 1) * 33 + j] = fminf(fmaxf(h1b, 0.0f), 1.0f);

    __syncthreads();

    // ---------------- FC2 + output head: warp w -> rows 2w, 2w+1 ----------------------
    const float b2j = __ldg(fc2_b + lane);
    const float fcw = __ldg(fco_w + lane);
    const float fcb = __ldg(fco_b);

    #pragma unroll
    for (int rr = 0; rr < 2; rr++) {
        const int row = warp * 2 + rr;
        float h2 = b2j;
        #pragma unroll
        for (int i = 0; i < 32; i++)
            h2 = fmaf(fc2T[i * 32 + lane], h1s[row * 33 + i], h2);
        h2 = fminf(fmaxf(h2, 0.0f), 1.0f);

        float o = h2 * fcw;
        #pragma unroll
        for (int off = 16; off; off >>= 1)
            o += __shfl_xor_sync(FULLMASK, o, off);

        if (lane == 0)
            out[row0 + row] = o + fcb;
    }
}

extern "C" void kernel_launch(void* const* d_in, const int* in_sizes, int n_in,
                              void* d_out, int out_size)
{
    const int*   wft_ics  = (const int*)  d_in[0];
    const float* wft_vals = (const float*)d_in[1];
    const int*   bft_ics  = (const int*)  d_in[2];
    const float* bft_vals = (const float*)d_in[3];
    const int*   stm      = (const int*)  d_in[4];
    const float* ft_w     = (const float*)d_in[5];
    const float* ft_b     = (const float*)d_in[6];
    const float* fc1_w    = (const float*)d_in[7];
    const float* fc1_b    = (const float*)d_in[8];
    const float* fc2_w    = (const float*)d_in[9];
    const float* fc2_b    = (const float*)d_in[10];
    const float* fco_w    = (const float*)d_in[11];
    const float* fco_b    = (const float*)d_in[12];
    float* out = (float*)d_out;

    // primary: table conversion + fc1 transpose
    prep_all<<<TBL_BLOCKS + 16, 256>>>(ft_w, fc1_w);

    // secondary with programmatic dependent launch: overlaps its staging with prep tail
    cudaLaunchConfig_t cfg = {};
    cfg.gridDim  = dim3(B_ROWS / TILE);
    cfg.blockDim = dim3(256);
    cfg.dynamicSmemBytes = 0;
    cfg.stream = 0;
    cudaLaunchAttribute attrs[1];
    attrs[0].id = cudaLaunchAttributeProgrammaticStreamSerialization;
    attrs[0].val.programmaticStreamSerializationAllowed = 1;
    cfg.attrs = attrs;
    cfg.numAttrs = 1;
    cudaLaunchKernelEx(&cfg, nnue_kernel,
                       wft_ics, wft_vals, bft_ics, bft_vals, stm,
                       ft_b, fc1_b, fc2_w, fc2_b, fco_w, fco_b, out);
}